// round 8
// baseline (speedup 1.0000x reference)
#include <cuda_runtime.h>

// 4-qubit depth-2 variational circuit, B=2^20 samples.
// prep: builds batch-independent tensor T_w[i0,i1,i2,i3] (81 float4).
// main: 2 samples/thread; f32x2 lanes hold WIRE PAIRS (w0,w1)/(w2,w3), so the
// T operand is the raw low/high half of the float4 shared load (no dup MOVs).
// Factored contraction:
//   z_w = sum_{i0} r0[i0] sum_{i1} r1[i1] sum_{i2} r2[i2] sum_{i3} r3[i3] T
// with r_q = (1, cos(x_q pi), sin(x_q pi)).

__device__ float4 g_T4[81];

#define PACKX2(d, lo, hi) \
    asm("mov.b64 %0, {%1, %2};" : "=l"(d) : "f"(lo), "f"(hi))
#define UNPACKX2(lo, hi, s) \
    asm("mov.b64 {%0, %1}, %2;" : "=f"(lo), "=f"(hi) : "l"(s))
#define FMAX2(d, a, b, c) \
    asm("fma.rn.f32x2 %0, %1, %2, %3;" : "=l"(d) : "l"(a), "l"(b), "l"(c))

// ---------------- prep ----------------
__global__ void __launch_bounds__(512) qc_prep_kernel(const float* __restrict__ w) {
    __shared__ float sUr[16][16], sUi[16][16];
    __shared__ float sA[4][16][16];
    int tid = threadIdx.x;

    if (tid < 16) {
        const int j = tid;
        float wv[16];
#pragma unroll
        for (int i = 0; i < 16; ++i) wv[i] = w[i];
        float re[16], im[16];
#pragma unroll
        for (int s = 0; s < 16; ++s) { re[s] = (s == j) ? 1.0f : 0.0f; im[s] = 0.0f; }
#pragma unroll
        for (int d = 0; d < 2; ++d) {
#pragma unroll
            for (int g = 0; g < 4; ++g) {
                const int cm = 8 >> g;
                const int tm = 8 >> ((g + 1) & 3);
                float tre[16], tim[16];
#pragma unroll
                for (int s = 0; s < 16; ++s) {
                    const int src = (s & cm) ? (s ^ tm) : s;
                    tre[s] = re[src]; tim[s] = im[src];
                }
#pragma unroll
                for (int s = 0; s < 16; ++s) { re[s] = tre[s]; im[s] = tim[s]; }
            }
#pragma unroll
            for (int qb = 0; qb < 4; ++qb) {
                const int m = 8 >> qb;
                float cy, sy; __sincosf(0.5f * wv[d * 8 + qb * 2 + 0], &sy, &cy);
#pragma unroll
                for (int s = 0; s < 16; ++s) {
                    if (s & m) continue;
                    const int s1 = s | m;
                    float r0 = re[s], i0 = im[s], r1 = re[s1], i1 = im[s1];
                    re[s]  = cy * r0 - sy * r1;  im[s]  = cy * i0 - sy * i1;
                    re[s1] = sy * r0 + cy * r1;  im[s1] = sy * i0 + cy * i1;
                }
                float cp, sp; __sincosf(0.5f * wv[d * 8 + qb * 2 + 1], &sp, &cp);
#pragma unroll
                for (int s = 0; s < 16; ++s) {
                    float r = re[s], i = im[s];
                    if (s & m) { re[s] = r * cp - i * sp;  im[s] = i * cp + r * sp; }
                    else       { re[s] = r * cp + i * sp;  im[s] = i * cp - r * sp; }
                }
            }
        }
#pragma unroll
        for (int s = 0; s < 16; ++s) { sUr[s][j] = re[s]; sUi[s][j] = im[s]; }
    }
    __syncthreads();

    for (int e = tid; e < 1024; e += 512) {
        int wq = e >> 8;
        int j  = (e >> 4) & 15;
        int jp = e & 15;
        int mask = 8 >> wq;
        float acc = 0.f;
#pragma unroll
        for (int s = 0; s < 16; ++s) {
            float v = sUr[s][j] * sUr[s][jp] + sUi[s][j] * sUi[s][jp];
            acc += (s & mask) ? -v : v;
        }
        sA[wq][j][jp] = acc;
    }
    __syncthreads();

    if (tid < 324) {
        int wq = tid / 81;
        int kl = tid - wq * 81;
        int k = kl / 9, l = kl % 9;
        int i0 = k / 3, i1 = k % 3, i2 = l / 3, i3 = l % 3;
        int x0 = (i0 == 2), x1 = (i1 == 2), x2 = (i2 == 2), x3 = (i3 == 2);
        int n0 = (i0 == 1), n1 = (i1 == 1), n2 = (i2 == 1), n3 = (i3 == 1);
        float acc = 0.f;
#pragma unroll
        for (int c = 0; c < 16; ++c) {
            int o0 = (c >> 3) & 1, o1 = (c >> 2) & 1, o2 = (c >> 1) & 1, o3 = c & 1;
            int j  = (o0 << 3) | (o1 << 2) | (o2 << 1) | o3;
            int jp = ((o0 ^ x0) << 3) | ((o1 ^ x1) << 2) | ((o2 ^ x2) << 1) | (o3 ^ x3);
            int neg = (n0 & o0) ^ (n1 & o1) ^ (n2 & o2) ^ (n3 & o3);
            float v = sA[wq][j][jp];
            acc += neg ? -v : v;
        }
        ((float*)g_T4)[kl * 4 + wq] = acc * (1.0f / 16.0f);
    }
}

// ---------------- main: 2 samples/thread, wire-pair lanes ----------------
__global__ void __launch_bounds__(256, 3) qc_main_kernel(
    const float4* __restrict__ x, float4* __restrict__ out, int h /* B/2 */) {
    // Ts[i] holds T4[i] as two b64 operands: .x = (T_w0,T_w1), .y = (T_w2,T_w3)
    __shared__ ulonglong2 Ts[81];
    int tid = threadIdx.x;
    if (tid < 81) {
        float4 v = g_T4[tid];
        ulonglong2 p;
        unsigned long long lo, hi;
        PACKX2(lo, v.x, v.y);
        PACKX2(hi, v.z, v.w);
        p.x = lo; p.y = hi;
        Ts[tid] = p;
    }
    __syncthreads();

    int t = blockIdx.x * 256 + tid;
    if (t >= h) return;

    const float PI_F = 3.14159265358979323846f;
    float4 xa = x[t];
    float4 xb = x[t + h];

    float Cf[2][4], Sf[2][4];  // [sample][qubit]
    __sincosf(xa.x * PI_F, &Sf[0][0], &Cf[0][0]);
    __sincosf(xa.y * PI_F, &Sf[0][1], &Cf[0][1]);
    __sincosf(xa.z * PI_F, &Sf[0][2], &Cf[0][2]);
    __sincosf(xa.w * PI_F, &Sf[0][3], &Cf[0][3]);
    __sincosf(xb.x * PI_F, &Sf[1][0], &Cf[1][0]);
    __sincosf(xb.y * PI_F, &Sf[1][1], &Cf[1][1]);
    __sincosf(xb.z * PI_F, &Sf[1][2], &Cf[1][2]);
    __sincosf(xb.w * PI_F, &Sf[1][3], &Cf[1][3]);

    // duplicated (c,c) b64 factors, per sample per qubit
    unsigned long long CA[4], SA[4], CB[4], SB[4];
#pragma unroll
    for (int qb = 0; qb < 4; ++qb) {
        PACKX2(CA[qb], Cf[0][qb], Cf[0][qb]);
        PACKX2(SA[qb], Sf[0][qb], Sf[0][qb]);
        PACKX2(CB[qb], Cf[1][qb], Cf[1][qb]);
        PACKX2(SB[qb], Sf[1][qb], Sf[1][qb]);
    }

    // accumulators: [sample][pair]  pair 0 = wires(0,1), pair 1 = wires(2,3)
    unsigned long long zA0, zA1, zB0, zB1;

#pragma unroll
    for (int i0 = 0; i0 < 3; ++i0) {
        unsigned long long tA0, tA1, tB0, tB1;
#pragma unroll
        for (int i1 = 0; i1 < 3; ++i1) {
            const int base = (i0 * 3 + i1) * 9;
            unsigned long long uA0, uA1, uB0, uB1;
#pragma unroll
            for (int i2 = 0; i2 < 3; ++i2) {
                ulonglong2 Ta = Ts[base + i2 * 3 + 0];
                ulonglong2 Tb = Ts[base + i2 * 3 + 1];
                ulonglong2 Tc = Ts[base + i2 * 3 + 2];
                // v = Ta + C3*Tb + S3*Tc  (per sample, per wire-pair)
                unsigned long long vA0, vA1, vB0, vB1;
                FMAX2(vA0, CA[3], Tb.x, Ta.x);
                FMAX2(vA1, CA[3], Tb.y, Ta.y);
                FMAX2(vB0, CB[3], Tb.x, Ta.x);
                FMAX2(vB1, CB[3], Tb.y, Ta.y);
                FMAX2(vA0, SA[3], Tc.x, vA0);
                FMAX2(vA1, SA[3], Tc.y, vA1);
                FMAX2(vB0, SB[3], Tc.x, vB0);
                FMAX2(vB1, SB[3], Tc.y, vB1);
                if (i2 == 0) { uA0 = vA0; uA1 = vA1; uB0 = vB0; uB1 = vB1; }
                else if (i2 == 1) {
                    FMAX2(uA0, CA[2], vA0, uA0);
                    FMAX2(uA1, CA[2], vA1, uA1);
                    FMAX2(uB0, CB[2], vB0, uB0);
                    FMAX2(uB1, CB[2], vB1, uB1);
                } else {
                    FMAX2(uA0, SA[2], vA0, uA0);
                    FMAX2(uA1, SA[2], vA1, uA1);
                    FMAX2(uB0, SB[2], vB0, uB0);
                    FMAX2(uB1, SB[2], vB1, uB1);
                }
            }
            if (i1 == 0) { tA0 = uA0; tA1 = uA1; tB0 = uB0; tB1 = uB1; }
            else if (i1 == 1) {
                FMAX2(tA0, CA[1], uA0, tA0);
                FMAX2(tA1, CA[1], uA1, tA1);
                FMAX2(tB0, CB[1], uB0, tB0);
                FMAX2(tB1, CB[1], uB1, tB1);
            } else {
                FMAX2(tA0, SA[1], uA0, tA0);
                FMAX2(tA1, SA[1], uA1, tA1);
                FMAX2(tB0, SB[1], uB0, tB0);
                FMAX2(tB1, SB[1], uB1, tB1);
            }
        }
        if (i0 == 0) { zA0 = tA0; zA1 = tA1; zB0 = tB0; zB1 = tB1; }
        else if (i0 == 1) {
            FMAX2(zA0, CA[0], tA0, zA0);
            FMAX2(zA1, CA[0], tA1, zA1);
            FMAX2(zB0, CB[0], tB0, zB0);
            FMAX2(zB1, CB[0], tB1, zB1);
        } else {
            FMAX2(zA0, SA[0], tA0, zA0);
            FMAX2(zA1, SA[0], tA1, zA1);
            FMAX2(zB0, SB[0], tB0, zB0);
            FMAX2(zB1, SB[0], tB1, zB1);
        }
    }

    float a0, a1, a2, a3, b0, b1, b2, b3;
    UNPACKX2(a0, a1, zA0);
    UNPACKX2(a2, a3, zA1);
    UNPACKX2(b0, b1, zB0);
    UNPACKX2(b2, b3, zB1);

    out[t]     = make_float4(a0, a1, a2, a3);
    out[t + h] = make_float4(b0, b1, b2, b3);
}

extern "C" void kernel_launch(void* const* d_in, const int* in_sizes, int n_in,
                              void* d_out, int out_size) {
    const float* x = (const float*)d_in[0];       // [B,4]
    const float* w = (const float*)d_in[1];       // [2,4,2]
    float* out = (float*)d_out;                   // [B,4]
    int B = in_sizes[0] / 4;
    int h = B / 2;

    qc_prep_kernel<<<1, 512>>>(w);
    int blocks = (h + 255) / 256;
    qc_main_kernel<<<blocks, 256>>>((const float4*)x, (float4*)out, h);
}

// round 9
// speedup vs baseline: 1.0014x; 1.0014x over previous
#include <cuda_runtime.h>

// 4-qubit depth-2 variational circuit, B=2^20 samples.
// prep (384 thr, amplitude-parallel): builds batch-independent tensor
// T_w[i0,i1,i2,i3] (81 float4, stored pre-packed as ulonglong2 wire-pairs).
// main: 2 samples/thread, wire-pair f32x2 lanes, factored contraction
//   z_w = sum_{i0} r0[i0] sum_{i1} r1[i1] sum_{i2} r2[i2] sum_{i3} r3[i3] T
// with explicit one-group-ahead prefetch of T from shared.

__device__ ulonglong2 g_T2[81];  // .x=(T_w0,T_w1) .y=(T_w2,T_w3)

#define PACKX2(d, lo, hi) \
    asm("mov.b64 %0, {%1, %2};" : "=l"(d) : "f"(lo), "f"(hi))
#define FMAX2(d, a, b, c) \
    asm("fma.rn.f32x2 %0, %1, %2, %3;" : "=l"(d) : "l"(a), "l"(b), "l"(c))

// ---------------- prep: amplitude-parallel ----------------
__global__ void __launch_bounds__(384) qc_prep_kernel(const float* __restrict__ w) {
    __shared__ float bufR[16][16], bufI[16][16];  // [state s][column j]
    __shared__ float sA[4][16][16];
    __shared__ float2 sTrig[16];                  // (cos, sin) of w[i]/2
    int tid = threadIdx.x;

    if (tid < 16) {
        float c, s;
        __sincosf(0.5f * w[tid], &s, &c);
        sTrig[tid] = make_float2(c, s);
    }

    // stage 1: 256 threads, one complex amplitude each. j = col, s = state row.
    const int j = tid & 15;
    const int s = tid >> 4;
    float ar = (s == j) ? 1.0f : 0.0f;
    float ai = 0.0f;
    __syncthreads();

#pragma unroll
    for (int d = 0; d < 2; ++d) {
        // composite CNOT ring permutation: new[s] = old[c0(c1(c2(c3(s))))]
        if (tid < 256) { bufR[s][j] = ar; bufI[s][j] = ai; }
        __syncthreads();
        if (tid < 256) {
            int src = s;
            if (src & 1) src ^= 8;   // c3: cm=1, tm=8
            if (src & 2) src ^= 1;   // c2: cm=2, tm=1
            if (src & 4) src ^= 2;   // c1: cm=4, tm=2
            if (src & 8) src ^= 4;   // c0: cm=8, tm=4
            ar = bufR[src][j]; ai = bufI[src][j];
        }
        __syncthreads();
#pragma unroll
        for (int q = 0; q < 4; ++q) {
            const int m = 8 >> q;
            float2 ty = sTrig[d * 8 + q * 2 + 0];  // RY half-angle (c,s)
            float2 tz = sTrig[d * 8 + q * 2 + 1];  // RZ half-angle (c,s)
            if (tid < 256) { bufR[s][j] = ar; bufI[s][j] = ai; }
            __syncthreads();
            if (tid < 256) {
                float pr = bufR[s ^ m][j], pi = bufI[s ^ m][j];
                float cy = ty.x, sy = ty.y, cp = tz.x, sp = tz.y;
                float nr, ni;
                if (s & m) { nr = cy * ar + sy * pr;  ni = cy * ai + sy * pi; }
                else       { nr = cy * ar - sy * pr;  ni = cy * ai - sy * pi; }
                // RZ (diagonal, local): bit=1 -> e^{+i p/2}, bit=0 -> e^{-i p/2}
                if (s & m) { ar = nr * cp - ni * sp;  ai = ni * cp + nr * sp; }
                else       { ar = nr * cp + ni * sp;  ai = ni * cp - nr * sp; }
            }
            __syncthreads();
        }
    }
    if (tid < 256) { bufR[s][j] = ar; bufI[s][j] = ai; }
    __syncthreads();

    // stage 2: A_w[jj][jp] = sum_s sign_w(s)*(Ur[s][jj]Ur[s][jp]+Ui[s][jj]Ui[s][jp])
    for (int e = tid; e < 1024; e += 384) {
        int wq = e >> 8;
        int jj = (e >> 4) & 15;
        int jp = e & 15;
        int mask = 8 >> wq;
        float acc = 0.f;
#pragma unroll
        for (int ss = 0; ss < 16; ++ss) {
            float v = bufR[ss][jj] * bufR[ss][jp] + bufI[ss][jj] * bufI[ss][jp];
            acc += (ss & mask) ? -v : v;
        }
        sA[wq][jj][jp] = acc;
    }
    __syncthreads();

    // stage 3: sparse basis change (16 nonzero (j,jp) pairs per (k,l)); write
    // packed wire-pair ulonglong2 directly.
    if (tid < 81) {
        int k = tid / 9, l = tid % 9;
        int i0 = k / 3, i1 = k % 3, i2 = l / 3, i3 = l % 3;
        int x0 = (i0 == 2), x1 = (i1 == 2), x2 = (i2 == 2), x3 = (i3 == 2);
        int n0 = (i0 == 1), n1 = (i1 == 1), n2 = (i2 == 1), n3 = (i3 == 1);
        float t4[4] = {0.f, 0.f, 0.f, 0.f};
#pragma unroll
        for (int c = 0; c < 16; ++c) {
            int o0 = (c >> 3) & 1, o1 = (c >> 2) & 1, o2 = (c >> 1) & 1, o3 = c & 1;
            int jj = (o0 << 3) | (o1 << 2) | (o2 << 1) | o3;
            int jp = ((o0 ^ x0) << 3) | ((o1 ^ x1) << 2) | ((o2 ^ x2) << 1) | (o3 ^ x3);
            int neg = (n0 & o0) ^ (n1 & o1) ^ (n2 & o2) ^ (n3 & o3);
            float sgn = neg ? -1.0f : 1.0f;
#pragma unroll
            for (int wq = 0; wq < 4; ++wq) t4[wq] += sgn * sA[wq][jj][jp];
        }
        const float inv16 = 1.0f / 16.0f;
        unsigned long long lo, hi;
        PACKX2(lo, t4[0] * inv16, t4[1] * inv16);
        PACKX2(hi, t4[2] * inv16, t4[3] * inv16);
        ulonglong2 p; p.x = lo; p.y = hi;
        g_T2[tid] = p;
    }
}

// ---------------- main: 2 samples/thread, wire-pair lanes, prefetch ----------------
__global__ void __launch_bounds__(256) qc_main_kernel(
    const float4* __restrict__ x, ulonglong2* __restrict__ out, int h /* B/2 */) {
    __shared__ ulonglong2 Ts[81];  // Ts[3g+c], g = (i0*3+i1)*3+i2, c in {a,b,c}
    int tid = threadIdx.x;
    if (tid < 81) Ts[tid] = g_T2[tid];
    __syncthreads();

    int t = blockIdx.x * 256 + tid;
    if (t >= h) return;

    const float PI_F = 3.14159265358979323846f;
    float4 xa = x[t];
    float4 xb = x[t + h];

    float Cf[2][4], Sf[2][4];
    __sincosf(xa.x * PI_F, &Sf[0][0], &Cf[0][0]);
    __sincosf(xa.y * PI_F, &Sf[0][1], &Cf[0][1]);
    __sincosf(xa.z * PI_F, &Sf[0][2], &Cf[0][2]);
    __sincosf(xa.w * PI_F, &Sf[0][3], &Cf[0][3]);
    __sincosf(xb.x * PI_F, &Sf[1][0], &Cf[1][0]);
    __sincosf(xb.y * PI_F, &Sf[1][1], &Cf[1][1]);
    __sincosf(xb.z * PI_F, &Sf[1][2], &Cf[1][2]);
    __sincosf(xb.w * PI_F, &Sf[1][3], &Cf[1][3]);

    unsigned long long CA[4], SA[4], CB[4], SB[4];
#pragma unroll
    for (int qb = 0; qb < 4; ++qb) {
        PACKX2(CA[qb], Cf[0][qb], Cf[0][qb]);
        PACKX2(SA[qb], Sf[0][qb], Sf[0][qb]);
        PACKX2(CB[qb], Cf[1][qb], Cf[1][qb]);
        PACKX2(SB[qb], Sf[1][qb], Sf[1][qb]);
    }

    unsigned long long zA0, zA1, zB0, zB1;

    // one-group-ahead prefetch
    ulonglong2 Na = Ts[0], Nb = Ts[1], Nc = Ts[2];

#pragma unroll
    for (int i0 = 0; i0 < 3; ++i0) {
        unsigned long long tA0, tA1, tB0, tB1;
#pragma unroll
        for (int i1 = 0; i1 < 3; ++i1) {
            unsigned long long uA0, uA1, uB0, uB1;
#pragma unroll
            for (int i2 = 0; i2 < 3; ++i2) {
                const int g = (i0 * 3 + i1) * 3 + i2;
                ulonglong2 Ta = Na, Tb = Nb, Tc = Nc;
                if (g < 26) {
                    Na = Ts[3 * (g + 1) + 0];
                    Nb = Ts[3 * (g + 1) + 1];
                    Nc = Ts[3 * (g + 1) + 2];
                }
                // v = Ta + C3*Tb + S3*Tc  (per sample, per wire-pair)
                unsigned long long vA0, vA1, vB0, vB1;
                FMAX2(vA0, CA[3], Tb.x, Ta.x);
                FMAX2(vA1, CA[3], Tb.y, Ta.y);
                FMAX2(vB0, CB[3], Tb.x, Ta.x);
                FMAX2(vB1, CB[3], Tb.y, Ta.y);
                FMAX2(vA0, SA[3], Tc.x, vA0);
                FMAX2(vA1, SA[3], Tc.y, vA1);
                FMAX2(vB0, SB[3], Tc.x, vB0);
                FMAX2(vB1, SB[3], Tc.y, vB1);
                if (i2 == 0) { uA0 = vA0; uA1 = vA1; uB0 = vB0; uB1 = vB1; }
                else if (i2 == 1) {
                    FMAX2(uA0, CA[2], vA0, uA0);
                    FMAX2(uA1, CA[2], vA1, uA1);
                    FMAX2(uB0, CB[2], vB0, uB0);
                    FMAX2(uB1, CB[2], vB1, uB1);
                } else {
                    FMAX2(uA0, SA[2], vA0, uA0);
                    FMAX2(uA1, SA[2], vA1, uA1);
                    FMAX2(uB0, SB[2], vB0, uB0);
                    FMAX2(uB1, SB[2], vB1, uB1);
                }
            }
            if (i1 == 0) { tA0 = uA0; tA1 = uA1; tB0 = uB0; tB1 = uB1; }
            else if (i1 == 1) {
                FMAX2(tA0, CA[1], uA0, tA0);
                FMAX2(tA1, CA[1], uA1, tA1);
                FMAX2(tB0, CB[1], uB0, tB0);
                FMAX2(tB1, CB[1], uB1, tB1);
            } else {
                FMAX2(tA0, SA[1], uA0, tA0);
                FMAX2(tA1, SA[1], uA1, tA1);
                FMAX2(tB0, SB[1], uB0, tB0);
                FMAX2(tB1, SB[1], uB1, tB1);
            }
        }
        if (i0 == 0) { zA0 = tA0; zA1 = tA1; zB0 = tB0; zB1 = tB1; }
        else if (i0 == 1) {
            FMAX2(zA0, CA[0], tA0, zA0);
            FMAX2(zA1, CA[0], tA1, zA1);
            FMAX2(zB0, CB[0], tB0, zB0);
            FMAX2(zB1, CB[0], tB1, zB1);
        } else {
            FMAX2(zA0, SA[0], tA0, zA0);
            FMAX2(zA1, SA[0], tA1, zA1);
            FMAX2(zB0, SB[0], tB0, zB0);
            FMAX2(zB1, SB[0], tB1, zB1);
        }
    }

    // wire-pair lanes are already in output order: (w0,w1),(w2,w3)
    ulonglong2 oa; oa.x = zA0; oa.y = zA1;
    ulonglong2 ob; ob.x = zB0; ob.y = zB1;
    out[t]     = oa;
    out[t + h] = ob;
}

extern "C" void kernel_launch(void* const* d_in, const int* in_sizes, int n_in,
                              void* d_out, int out_size) {
    const float* x = (const float*)d_in[0];       // [B,4]
    const float* w = (const float*)d_in[1];       // [2,4,2]
    int B = in_sizes[0] / 4;
    int h = B / 2;

    qc_prep_kernel<<<1, 384>>>(w);
    int blocks = (h + 255) / 256;
    qc_main_kernel<<<blocks, 256>>>((const float4*)x, (ulonglong2*)d_out, h);
}